// round 7
// baseline (speedup 1.0000x reference)
#include <cuda_runtime.h>

#define NN 100000
#define EE 1600000
#define LL 3
#define CAP 96
#define NPB 64                      // nodes per block in kA/kB
#define PAD 68                      // y_s row stride (floats), 16B-aligned

typedef unsigned long long ull;

// ---------------- device scratch ----------------------------------------------
__device__ float g_h[NN * 64];
__device__ float g_z1[NN * 64];
__device__ float g_z2[NN * 64];
__device__ float g_stats[LL * 256];   // per layer: [sum1 sq1 sum2 sq2] x 64
__device__ int   g_deg[NN];
__device__ int   g_csr[(size_t)NN * CAP];

// ---------------- packed f32x2 helpers ----------------------------------------
__device__ __forceinline__ ull pack2(float a, float b) {
    ull r;
    asm("mov.b64 %0, {%1, %2};" : "=l"(r) : "f"(a), "f"(b));
    return r;
}
__device__ __forceinline__ float2 unpack2(ull v) {
    float2 r;
    asm("mov.b64 {%0, %1}, %2;" : "=f"(r.x), "=f"(r.y) : "l"(v));
    return r;
}
__device__ __forceinline__ void ffma2(ull& d, ull a, ull b) {
    asm("fma.rn.f32x2 %0, %1, %2, %0;" : "+l"(d) : "l"(a), "l"(b));
}

// ---------------- zero degree + stats -----------------------------------------
__global__ void __launch_bounds__(1024) kzero() {
    int t = blockIdx.x * 1024 + threadIdx.x;
    if (t < NN) g_deg[t] = 0;
    if (t < LL * 256) g_stats[t] = 0.f;
}

// ---------------- CSR fill ------------------------------------------------------
__global__ void __launch_bounds__(256) kfill(const int* __restrict__ ei) {
    int e = blockIdx.x * 256 + threadIdx.x;
    if (e >= EE) return;
    int s = ei[e];
    int d = ei[EE + e];
    int pos = atomicAdd(&g_deg[d], 1);
    if (pos < CAP) g_csr[(size_t)d * CAP + pos] = s;
}

// ---------------- kinit: logits = x @ fcW[0] + sum_l fcb[l] --------------------
__global__ void __launch_bounds__(256) kinit(const float* __restrict__ x,
                                             const float* __restrict__ fcW,
                                             const float* __restrict__ fcb,
                                             float* __restrict__ out) {
    __shared__ float fw[640];
    __shared__ float bsum[10];
    int tid = threadIdx.x;
    for (int i = tid; i < 640; i += 256) fw[i] = fcW[i];
    if (tid < 10) {
        float b = 0.f;
        for (int l = 0; l < LL + 1; l++) b += fcb[l * 10 + tid];
        bsum[tid] = b;
    }
    __syncthreads();
    int n = blockIdx.x * 256 + tid;
    if (n >= NN) return;
    float acc[10];
#pragma unroll
    for (int c = 0; c < 10; c++) acc[c] = bsum[c];
    const float4* x4 = ((const float4*)x) + (size_t)n * 16;
#pragma unroll
    for (int kk = 0; kk < 16; kk++) {
        float4 v = x4[kk];
        const float* r0 = fw + (kk * 4) * 10;
#pragma unroll
        for (int c = 0; c < 10; c++)
            acc[c] += v.x * r0[c] + v.y * r0[10 + c] + v.z * r0[20 + c] + v.w * r0[30 + c];
    }
#pragma unroll
    for (int c = 0; c < 10; c++) out[n * 10 + c] = acc[c];
}

// ---- shared GEMM tail: y_s(64xNPB, k-major) @ Wsh(64x64) + bias ----------------
__device__ __forceinline__ void gemm_tile(const float* y_s, const float* Wsh,
                                          const float* bs, int cg, int ng,
                                          ull acc[4][2]) {
#pragma unroll
    for (int c = 0; c < 4; c++) {
        float b = bs[4 * cg + c];
        acc[c][0] = pack2(b, b);
        acc[c][1] = acc[c][0];
    }
#pragma unroll 8
    for (int k = 0; k < 64; k++) {
        ulonglong2 a2 = ((const ulonglong2*)(y_s + k * PAD))[ng];
        float4 w = *(const float4*)(Wsh + k * 64 + cg * 4);
        ull w0 = pack2(w.x, w.x);
        ull w1 = pack2(w.y, w.y);
        ull w2 = pack2(w.z, w.z);
        ull w3 = pack2(w.w, w.w);
        ffma2(acc[0][0], a2.x, w0); ffma2(acc[0][1], a2.y, w0);
        ffma2(acc[1][0], a2.x, w1); ffma2(acc[1][1], a2.y, w1);
        ffma2(acc[2][0], a2.x, w2); ffma2(acc[2][1], a2.y, w2);
        ffma2(acc[3][0], a2.x, w3); ffma2(acc[3][1], a2.y, w3);
    }
}

// ---- shared epilogue: unpack, store z, shfl-reduce stats, atomics --------------
__device__ __forceinline__ void store_stats(ull acc[4][2], float* zout, int base,
                                            int ng, int cg, int lane,
                                            float* stat_s, float* stat_q) {
    float val[4][4];
#pragma unroll
    for (int c = 0; c < 4; c++) {
        float2 lo = unpack2(acc[c][0]);
        float2 hi = unpack2(acc[c][1]);
        val[c][0] = lo.x; val[c][1] = lo.y; val[c][2] = hi.x; val[c][3] = hi.y;
    }
    float s[4] = {0.f, 0.f, 0.f, 0.f};
    float q[4] = {0.f, 0.f, 0.f, 0.f};
#pragma unroll
    for (int i = 0; i < 4; i++) {
        int n = base + 4 * ng + i;
        if (n < NN) {
            float4 o = make_float4(val[0][i], val[1][i], val[2][i], val[3][i]);
            *(float4*)(zout + (size_t)n * 64 + 4 * cg) = o;
#pragma unroll
            for (int c = 0; c < 4; c++) {
                float v = val[c][i];
                s[c] += v;
                q[c] += v * v;
            }
        }
    }
#pragma unroll
    for (int off = 8; off >= 1; off >>= 1) {
#pragma unroll
        for (int c = 0; c < 4; c++) {
            s[c] += __shfl_xor_sync(0xffffffffu, s[c], off);
            q[c] += __shfl_xor_sync(0xffffffffu, q[c], off);
        }
    }
    if ((lane & 15) == 0) {
#pragma unroll
        for (int c = 0; c < 4; c++) {
            atomicAdd(&stat_s[4 * cg + c], s[c]);
            atomicAdd(&stat_q[4 * cg + c], q[c]);
        }
    }
}

__device__ __forceinline__ void f4add(float4& a, float4 b) {
    a.x += b.x; a.y += b.y; a.z += b.z; a.w += b.w;
}

// ======== kA: CSR gather (half-warp/node, LDG.128 x4 MLP) + GEMM1 + stats1 ======
__global__ void __launch_bounds__(256) kA(const float* __restrict__ x, int use_x,
                                          const float* __restrict__ W,
                                          const float* __restrict__ b, int layer) {
    __shared__ float y_s[64 * PAD];
    __shared__ float Wsh[4096];
    __shared__ float bs[64];
    int tid = threadIdx.x, lane = tid & 31, wid = tid >> 5;
    for (int i = tid; i < 4096; i += 256) Wsh[i] = W[i];
    if (tid < 64) bs[tid] = b[tid];
    const float* hin = use_x ? x : g_h;
    int base = blockIdx.x * NPB;

    int hf = lane >> 4;    // half-warp id
    int sl = lane & 15;    // float4 slot within row

    // each half-warp gathers one node per iteration; 4 iterations = 8 nodes/warp
#pragma unroll 1
    for (int j = 0; j < 4; j++) {
        int nl = wid * 8 + 2 * j + hf;
        int n = base + nl;
        float4 a0 = make_float4(0.f, 0.f, 0.f, 0.f);
        float4 a1 = a0, a2 = a0, a3 = a0;
        if (n < NN) {
            a0 = ((const float4*)(hin + (size_t)n * 64))[sl];
            int deg = g_deg[n];
            if (deg > CAP) deg = CAP;
            const int* adj = g_csr + (size_t)n * CAP;
            int e = 0;
            for (; e + 4 <= deg; e += 4) {
                int4 nb = *(const int4*)(adj + e);
                float4 v0 = ((const float4*)(hin + (size_t)nb.x * 64))[sl];
                float4 v1 = ((const float4*)(hin + (size_t)nb.y * 64))[sl];
                float4 v2 = ((const float4*)(hin + (size_t)nb.z * 64))[sl];
                float4 v3 = ((const float4*)(hin + (size_t)nb.w * 64))[sl];
                f4add(a0, v0); f4add(a1, v1); f4add(a2, v2); f4add(a3, v3);
            }
            for (; e < deg; e++) {
                float4 v = ((const float4*)(hin + (size_t)adj[e] * 64))[sl];
                f4add(a0, v);
            }
            f4add(a1, a2);
            f4add(a0, a3);
            f4add(a0, a1);
        }
        int k0 = 4 * sl;
        y_s[(k0 + 0) * PAD + nl] = a0.x;
        y_s[(k0 + 1) * PAD + nl] = a0.y;
        y_s[(k0 + 2) * PAD + nl] = a0.z;
        y_s[(k0 + 3) * PAD + nl] = a0.w;
    }
    __syncthreads();

    int ng = tid & 15, cg = tid >> 4;
    ull acc[4][2];
    gemm_tile(y_s, Wsh, bs, cg, ng, acc);
    store_stats(acc, g_z1, base, ng, cg, lane,
                g_stats + layer * 256, g_stats + layer * 256 + 64);
}

// ======== kB: BN1+ReLU (float4) -> smem(T) -> GEMM2 -> z2 + stats2 ==============
__global__ void __launch_bounds__(256) kB(const float* __restrict__ W,
                                          const float* __restrict__ b,
                                          const float* __restrict__ gam,
                                          const float* __restrict__ bet, int layer) {
    __shared__ float y_s[64 * PAD];
    __shared__ float Wsh[4096];
    __shared__ float bs[64], sA[64], sB[64];
    int tid = threadIdx.x, lane = tid & 31, wid = tid >> 5;
    for (int i = tid; i < 4096; i += 256) Wsh[i] = W[i];
    if (tid < 64) {
        float s = g_stats[layer * 256 + tid];
        float q = g_stats[layer * 256 + 64 + tid];
        float mu = s * (1.f / NN);
        float var = q * (1.f / NN) - mu * mu;
        float a = rsqrtf(var + 1e-5f) * gam[tid];
        sA[tid] = a;
        sB[tid] = bet[tid] - mu * a;
        bs[tid] = b[tid];
    }
    __syncthreads();
    int base = blockIdx.x * NPB;
    int hf = lane >> 4, sl = lane & 15;
    int k0 = 4 * sl;

#pragma unroll 2
    for (int j = 0; j < 4; j++) {
        int nl = wid * 8 + 2 * j + hf;
        int n = base + nl;
        float4 a0 = make_float4(0.f, 0.f, 0.f, 0.f);
        if (n < NN) {
            float4 v = ((const float4*)(g_z1 + (size_t)n * 64))[sl];
            a0.x = fmaxf(fmaf(v.x, sA[k0 + 0], sB[k0 + 0]), 0.f);
            a0.y = fmaxf(fmaf(v.y, sA[k0 + 1], sB[k0 + 1]), 0.f);
            a0.z = fmaxf(fmaf(v.z, sA[k0 + 2], sB[k0 + 2]), 0.f);
            a0.w = fmaxf(fmaf(v.w, sA[k0 + 3], sB[k0 + 3]), 0.f);
        }
        y_s[(k0 + 0) * PAD + nl] = a0.x;
        y_s[(k0 + 1) * PAD + nl] = a0.y;
        y_s[(k0 + 2) * PAD + nl] = a0.z;
        y_s[(k0 + 3) * PAD + nl] = a0.w;
    }
    __syncthreads();

    int ng = tid & 15, cg = tid >> 4;
    ull acc[4][2];
    gemm_tile(y_s, Wsh, bs, cg, ng, acc);
    store_stats(acc, g_z2, base, ng, cg, lane,
                g_stats + layer * 256 + 128, g_stats + layer * 256 + 192);
}

// ======== kC: BN2+ReLU -> h; logits += h @ fcW[layer+1]; optional softmax =======
__global__ void __launch_bounds__(256) kC(const float* __restrict__ gam,
                                          const float* __restrict__ bet,
                                          const float* __restrict__ fcW,
                                          int layer, int final_layer,
                                          float* __restrict__ out) {
    __shared__ float fw[640];
    __shared__ float sA[64], sB[64];
    int tid = threadIdx.x;
    const float* fsrc = fcW + (layer + 1) * 640;
    for (int i = tid; i < 640; i += 256) fw[i] = fsrc[i];
    if (tid < 64) {
        float s = g_stats[layer * 256 + 128 + tid];
        float q = g_stats[layer * 256 + 192 + tid];
        float mu = s * (1.f / NN);
        float var = q * (1.f / NN) - mu * mu;
        float a = rsqrtf(var + 1e-5f) * gam[tid];
        sA[tid] = a;
        sB[tid] = bet[tid] - mu * a;
    }
    __syncthreads();
    int n = blockIdx.x * 256 + tid;
    if (n >= NN) return;
    float o[10];
#pragma unroll
    for (int c = 0; c < 10; c++) o[c] = out[n * 10 + c];
    const float4* z4 = ((const float4*)g_z2) + (size_t)n * 16;
    float4* hout = ((float4*)g_h) + (size_t)n * 16;
#pragma unroll
    for (int kk = 0; kk < 16; kk++) {
        float4 v = z4[kk];
        int k0 = kk * 4;
        float h0 = fmaxf(fmaf(v.x, sA[k0 + 0], sB[k0 + 0]), 0.f);
        float h1 = fmaxf(fmaf(v.y, sA[k0 + 1], sB[k0 + 1]), 0.f);
        float h2 = fmaxf(fmaf(v.z, sA[k0 + 2], sB[k0 + 2]), 0.f);
        float h3 = fmaxf(fmaf(v.w, sA[k0 + 3], sB[k0 + 3]), 0.f);
        if (!final_layer) hout[kk] = make_float4(h0, h1, h2, h3);
        const float* r0 = fw + k0 * 10;
#pragma unroll
        for (int c = 0; c < 10; c++)
            o[c] += h0 * r0[c] + h1 * r0[10 + c] + h2 * r0[20 + c] + h3 * r0[30 + c];
    }
    if (final_layer) {
        float m = -1e30f;
#pragma unroll
        for (int c = 0; c < 10; c++) m = fmaxf(m, o[c]);
        float s = 0.f;
#pragma unroll
        for (int c = 0; c < 10; c++) s += expf(o[c] - m);
        float lse = m + logf(s);
#pragma unroll
        for (int c = 0; c < 10; c++) o[c] -= lse;
    }
#pragma unroll
    for (int c = 0; c < 10; c++) out[n * 10 + c] = o[c];
}

// ---------------- launch --------------------------------------------------------
extern "C" void kernel_launch(void* const* d_in, const int* in_sizes, int n_in,
                              void* d_out, int out_size) {
    const float* x   = (const float*)d_in[0];
    const int*   ei  = (const int*)d_in[1];
    const float* W1  = (const float*)d_in[2];
    const float* b1  = (const float*)d_in[3];
    const float* g1  = (const float*)d_in[4];
    const float* be1 = (const float*)d_in[5];
    const float* W2  = (const float*)d_in[6];
    const float* b2  = (const float*)d_in[7];
    const float* gbn = (const float*)d_in[8];
    const float* bbn = (const float*)d_in[9];
    const float* fcW = (const float*)d_in[10];
    const float* fcb = (const float*)d_in[11];
    float* out = (float*)d_out;

    const int AB = (NN + NPB - 1) / NPB;  // 1563
    const int CB = (NN + 255) / 256;      // 391

    kzero<<<(NN + 1023) / 1024, 1024>>>();
    kfill<<<(EE + 255) / 256, 256>>>(ei);
    kinit<<<CB, 256>>>(x, fcW, fcb, out);
    for (int l = 0; l < LL; l++) {
        int use_x = (l == 0) ? 1 : 0;
        kA<<<AB, 256>>>(x, use_x, W1 + l * 4096, b1 + l * 64, l);
        kB<<<AB, 256>>>(W2 + l * 4096, b2 + l * 64, g1 + l * 64, be1 + l * 64, l);
        kC<<<CB, 256>>>(gbn + l * 64, bbn + l * 64, fcW, l, (l == LL - 1) ? 1 : 0, out);
    }
}